// round 12
// baseline (speedup 1.0000x reference)
#include <cuda_runtime.h>
#include <cuda_bf16.h>
#include <cstdint>

#define NP 100      // proxies
#define NS 1024     // samples
#define NN 1124     // total nodes
#define MPAD 1152   // NN padded to 128
#define D  512
#define PSPLIT 9    // proxy-agg split-K factor (9 x 128 = 1152)

// scratch (device globals; no allocation allowed)
__device__ float g_HW[MPAD * D];
__device__ float g_lp[8][NN][2];        // logit partials [64col-tile][node][src/dst]
__device__ float g_ppart[PSPLIT][128][D];
// bf16 split operands
__device__ __nv_bfloat16 g_Ah[MPAD * D];
__device__ __nv_bfloat16 g_Al[MPAD * D];
__device__ __nv_bfloat16 g_W1h[D * D];
__device__ __nv_bfloat16 g_W1l[D * D];
__device__ __nv_bfloat16 g_W2h[D * D];
__device__ __nv_bfloat16 g_W2l[D * D];
__device__ __nv_bfloat16 g_FCh[128 * D];
__device__ __nv_bfloat16 g_FCl[128 * D];
__device__ __nv_bfloat16 g_Hth[D * MPAD];   // H transposed [d][node]
__device__ __nv_bfloat16 g_Htl[D * MPAD];
__device__ __nv_bfloat16 g_aPh[128 * MPAD]; // alpha (proxy dst), K over all nodes, self on diag
__device__ __nv_bfloat16 g_aPl[128 * MPAD];

__device__ __forceinline__ float lrelu(float v) { return v > 0.f ? v : 0.2f * v; }

__device__ __forceinline__ uint32_t smem_u32(const void* p) {
    uint32_t a;
    asm("{ .reg .u64 t; cvta.to.shared.u64 t, %1; cvt.u32.u64 %0, t; }" : "=r"(a) : "l"(p));
    return a;
}
__device__ __forceinline__ void bsplit(float v, __nv_bfloat16& hi, __nv_bfloat16& lo) {
    hi = __float2bfloat16(v);
    lo = __float2bfloat16(v - __bfloat162float(hi));
}

// ============================ setup: W splits + input convert ============================
__global__ void k_setup(const float* __restrict__ W1, const float* __restrict__ W2,
                        const float* __restrict__ fcw,
                        const float* __restrict__ x, const float* __restrict__ prox) {
    int b = blockIdx.x;
    if (b < 512) {
        const float* W = (b >= 256) ? W2 : W1;
        __nv_bfloat16* Wh = (b >= 256) ? g_W2h : g_W1h;
        __nv_bfloat16* Wl = (b >= 256) ? g_W2l : g_W1l;
        int bb = b & 255;
        __shared__ float t[32][33];
        int tx = threadIdx.x & 31, ty = threadIdx.x >> 5;
        int n0 = (bb & 15) * 32, k0 = (bb >> 4) * 32;
        #pragma unroll
        for (int j = 0; j < 4; j++)
            t[ty + 8 * j][tx] = W[(size_t)(k0 + ty + 8 * j) * D + n0 + tx];
        __syncthreads();
        #pragma unroll
        for (int j = 0; j < 4; j++) {
            int n = n0 + ty + 8 * j, k = k0 + tx;
            __nv_bfloat16 hi, lo;
            bsplit(t[tx][ty + 8 * j], hi, lo);
            Wh[(size_t)n * D + k] = hi;
            Wl[(size_t)n * D + k] = lo;
        }
    } else if (b < 576) {
        int bb = b - 512;
        __shared__ float t[32][33];
        int tx = threadIdx.x & 31, ty = threadIdx.x >> 5;
        int n0 = (bb & 3) * 32, k0 = (bb >> 2) * 32;
        #pragma unroll
        for (int j = 0; j < 4; j++) {
            int n = n0 + tx;
            t[ty + 8 * j][tx] = (n < 100) ? fcw[(size_t)(k0 + ty + 8 * j) * 100 + n] : 0.f;
        }
        __syncthreads();
        #pragma unroll
        for (int j = 0; j < 4; j++) {
            int n = n0 + ty + 8 * j, k = k0 + tx;
            __nv_bfloat16 hi, lo;
            bsplit(t[tx][ty + 8 * j], hi, lo);
            g_FCh[(size_t)n * D + k] = hi;
            g_FCl[(size_t)n * D + k] = lo;
        }
    } else {
        int row = (b - 576) * 2 + (threadIdx.x >> 7);
        int c4 = (threadIdx.x & 127) * 4;
        int base = row * D + c4;
        float4 v = make_float4(0.f, 0.f, 0.f, 0.f);
        if (row < NP)      v = *reinterpret_cast<const float4*>(prox + base);
        else if (row < NN) v = *reinterpret_cast<const float4*>(x + base - NP * D);
        __nv_bfloat16 h0, h1, h2, h3, l0, l1, l2, l3;
        bsplit(v.x, h0, l0); bsplit(v.y, h1, l1); bsplit(v.z, h2, l2); bsplit(v.w, h3, l3);
        *reinterpret_cast<__nv_bfloat162*>(g_Ah + base)     = __nv_bfloat162(h0, h1);
        *reinterpret_cast<__nv_bfloat162*>(g_Ah + base + 2) = __nv_bfloat162(h2, h3);
        *reinterpret_cast<__nv_bfloat162*>(g_Al + base)     = __nv_bfloat162(l0, l1);
        *reinterpret_cast<__nv_bfloat162*>(g_Al + base + 2) = __nv_bfloat162(l2, l3);
    }
}

// ============================ mma common ============================
#define SWB(r, b) ((r) * 128 + ((b) ^ (((r) & 7) << 4)))
#define STAGE_BYTES 32768

__device__ __forceinline__ void ldm_x4(uint32_t* f, uint32_t addr) {
    asm volatile("ldmatrix.sync.aligned.m8n8.x4.shared.b16 {%0,%1,%2,%3}, [%4];"
                 : "=r"(f[0]), "=r"(f[1]), "=r"(f[2]), "=r"(f[3]) : "r"(addr));
}
__device__ __forceinline__ void ldm_x2(uint32_t* f, uint32_t addr) {
    asm volatile("ldmatrix.sync.aligned.m8n8.x2.shared.b16 {%0,%1}, [%2];"
                 : "=r"(f[0]), "=r"(f[1]) : "r"(addr));
}
__device__ __forceinline__ void mma_bf16(float* c, const uint32_t* a, const uint32_t* b) {
    asm volatile(
        "mma.sync.aligned.m16n8k16.row.col.f32.bf16.bf16.f32 "
        "{%0,%1,%2,%3}, {%4,%5,%6,%7}, {%8,%9}, {%0,%1,%2,%3};"
        : "+f"(c[0]), "+f"(c[1]), "+f"(c[2]), "+f"(c[3])
        : "r"(a[0]), "r"(a[1]), "r"(a[2]), "r"(a[3]), "r"(b[0]), "r"(b[1]));
}
__device__ __forceinline__ void cpa16(uint32_t saddr, const void* g) {
    asm volatile("cp.async.cg.shared.global [%0], [%1], 16;" :: "r"(saddr), "l"(g));
}

#define MMA_MAINLOOP(AH, AL, BH, BL, LDA, LDB, NCHUNK, KOFF)                             \
    int li = tid * 2;                                                                    \
    int lr0 = li >> 3, ls0 = li & 7;                                                     \
    int lr1 = (li + 1) >> 3, ls1 = (li + 1) & 7;                                         \
    int a_r = (lane & 7) + ((lane >> 3) & 1) * 8;                                        \
    int a_kb = (lane >> 4) * 16;                                                         \
    int b_r = lane & 7;                                                                  \
    int b_kb = ((lane >> 3) & 1) * 16;                                                   \
    float acc[2][2][4] = {};                                                             \
    auto issue = [&](int c, int st) {                                                    \
        int kc = (KOFF) + c * 64;                                                        \
        uint32_t stb = sb + st * STAGE_BYTES;                                            \
        cpa16(stb + SWB(lr0, ls0 * 16), (AH) + (size_t)(m0 + lr0) * (LDA) + kc + ls0 * 8); \
        cpa16(stb + SWB(lr1, ls1 * 16), (AH) + (size_t)(m0 + lr1) * (LDA) + kc + ls1 * 8); \
        cpa16(stb + 8192 + SWB(lr0, ls0 * 16), (AL) + (size_t)(m0 + lr0) * (LDA) + kc + ls0 * 8); \
        cpa16(stb + 8192 + SWB(lr1, ls1 * 16), (AL) + (size_t)(m0 + lr1) * (LDA) + kc + ls1 * 8); \
        cpa16(stb + 16384 + SWB(lr0, ls0 * 16), (BH) + (size_t)(n0 + lr0) * (LDB) + kc + ls0 * 8); \
        cpa16(stb + 16384 + SWB(lr1, ls1 * 16), (BH) + (size_t)(n0 + lr1) * (LDB) + kc + ls1 * 8); \
        cpa16(stb + 24576 + SWB(lr0, ls0 * 16), (BL) + (size_t)(n0 + lr0) * (LDB) + kc + ls0 * 8); \
        cpa16(stb + 24576 + SWB(lr1, ls1 * 16), (BL) + (size_t)(n0 + lr1) * (LDB) + kc + ls1 * 8); \
        asm volatile("cp.async.commit_group;");                                          \
    };                                                                                   \
    issue(0, 0);                                                                         \
    asm volatile("cp.async.wait_group 0;");                                              \
    __syncthreads();                                                                     \
    for (int c = 0; c < (NCHUNK); c++) {                                                 \
        int st = c & 1;                                                                  \
        if (c + 1 < (NCHUNK)) issue(c + 1, st ^ 1);                                      \
        uint32_t stb = sb + st * STAGE_BYTES;                                            \
        _Pragma("unroll")                                                                \
        for (int ks = 0; ks < 4; ks++) {                                                 \
            int kb = ks * 32;                                                            \
            uint32_t ah[2][4], al[2][4], bh[2][2], bl[2][2];                             \
            _Pragma("unroll")                                                            \
            for (int mt = 0; mt < 2; mt++) {                                             \
                int r = wm + mt * 16 + a_r;                                              \
                ldm_x4(ah[mt], stb + 0    + SWB(r, kb + a_kb));                          \
                ldm_x4(al[mt], stb + 8192 + SWB(r, kb + a_kb));                          \
            }                                                                            \
            _Pragma("unroll")                                                            \
            for (int nt = 0; nt < 2; nt++) {                                             \
                int r = wn + nt * 8 + b_r;                                               \
                ldm_x2(bh[nt], stb + 16384 + SWB(r, kb + b_kb));                         \
                ldm_x2(bl[nt], stb + 24576 + SWB(r, kb + b_kb));                         \
            }                                                                            \
            _Pragma("unroll")                                                            \
            for (int mt = 0; mt < 2; mt++)                                               \
                _Pragma("unroll")                                                        \
                for (int nt = 0; nt < 2; nt++) {                                         \
                    mma_bf16(acc[mt][nt], ah[mt], bh[nt]);                               \
                    mma_bf16(acc[mt][nt], ah[mt], bl[nt]);                               \
                    mma_bf16(acc[mt][nt], al[mt], bh[nt]);                               \
                }                                                                        \
        }                                                                                \
        if (c + 1 < (NCHUNK)) asm volatile("cp.async.wait_group 0;");                    \
        __syncthreads();                                                                 \
    }

// ============================ layer GEMM / FC GEMM ============================
__global__ void __launch_bounds__(256, 2) k_mma(
    const __nv_bfloat16* __restrict__ Ah, const __nv_bfloat16* __restrict__ Al,
    const __nv_bfloat16* __restrict__ Bh, const __nv_bfloat16* __restrict__ Bl,
    float* __restrict__ C, const float* __restrict__ bias, int mode,
    const float* __restrict__ asrc, const float* __restrict__ adst) {
    extern __shared__ __align__(16) char sm[];
    int tid = threadIdx.x, wid = tid >> 5, lane = tid & 31;
    int n0 = blockIdx.x * 64, m0 = blockIdx.y * 64;
    int wm = (wid >> 2) * 32, wn = (wid & 3) * 16;
    uint32_t sb = smem_u32(sm);

    MMA_MAINLOOP(Ah, Al, Bh, Bl, D, D, 8, 0)

    if (mode == 0) {
        #pragma unroll
        for (int mt = 0; mt < 2; mt++) {
            int row = m0 + wm + mt * 16 + (lane >> 2);
            #pragma unroll
            for (int nt = 0; nt < 2; nt++) {
                int col = n0 + wn + nt * 8 + (lane & 3) * 2;
                if (col >= 100) continue;
                float b0 = bias[col], b1 = bias[col + 1];
                *reinterpret_cast<float2*>(C + (size_t)row * 100 + col) =
                    make_float2(acc[mt][nt][0] + b0, acc[mt][nt][1] + b1);
                *reinterpret_cast<float2*>(C + (size_t)(row + 8) * 100 + col) =
                    make_float2(acc[mt][nt][2] + b0, acc[mt][nt][3] + b1);
            }
        }
        return;
    }

    // fp32 HW store
    #pragma unroll
    for (int mt = 0; mt < 2; mt++) {
        int row = m0 + wm + mt * 16 + (lane >> 2);
        #pragma unroll
        for (int nt = 0; nt < 2; nt++) {
            int col = n0 + wn + nt * 8 + (lane & 3) * 2;
            *reinterpret_cast<float2*>(g_HW + (size_t)row * D + col) =
                make_float2(acc[mt][nt][0], acc[mt][nt][1]);
            *reinterpret_cast<float2*>(g_HW + (size_t)(row + 8) * D + col) =
                make_float2(acc[mt][nt][2], acc[mt][nt][3]);
        }
    }

    // logit partials
    {
        float* lpb = reinterpret_cast<float*>(sm);   // [64][4][2]
        #pragma unroll
        for (int mt = 0; mt < 2; mt++)
            #pragma unroll
            for (int half = 0; half < 2; half++) {
                int rl = wm + mt * 16 + (lane >> 2) + half * 8;
                float s = 0.f, t = 0.f;
                #pragma unroll
                for (int nt = 0; nt < 2; nt++) {
                    int col = n0 + wn + nt * 8 + (lane & 3) * 2;
                    float v0 = acc[mt][nt][half * 2], v1 = acc[mt][nt][half * 2 + 1];
                    s += v0 * asrc[col] + v1 * asrc[col + 1];
                    t += v0 * adst[col] + v1 * adst[col + 1];
                }
                s += __shfl_xor_sync(0xffffffffu, s, 1);
                s += __shfl_xor_sync(0xffffffffu, s, 2);
                t += __shfl_xor_sync(0xffffffffu, t, 1);
                t += __shfl_xor_sync(0xffffffffu, t, 2);
                if ((lane & 3) == 0) {
                    lpb[(rl * 4 + (wid & 3)) * 2 + 0] = s;
                    lpb[(rl * 4 + (wid & 3)) * 2 + 1] = t;
                }
            }
        __syncthreads();
        if (tid < 128) {
            int rl = tid >> 1, comp = tid & 1;
            int row = m0 + rl;
            if (row < NN) {
                float s = lpb[(rl * 4 + 0) * 2 + comp] + lpb[(rl * 4 + 1) * 2 + comp]
                        + lpb[(rl * 4 + 2) * 2 + comp] + lpb[(rl * 4 + 3) * 2 + comp];
                g_lp[n0 >> 6][row][comp] = s;
            }
        }
        __syncthreads();
    }

    // transpose via smem, write Ht bf16 split
    float* ts = reinterpret_cast<float*>(sm);   // [64][65]
    #pragma unroll
    for (int mt = 0; mt < 2; mt++)
        #pragma unroll
        for (int nt = 0; nt < 2; nt++)
            #pragma unroll
            for (int j = 0; j < 4; j++) {
                int rl = wm + mt * 16 + (lane >> 2) + (j >> 1) * 8;
                int cl = wn + nt * 8 + (lane & 3) * 2 + (j & 1);
                ts[rl * 65 + cl] = acc[mt][nt][j];
            }
    __syncthreads();
    #pragma unroll
    for (int it = 0; it < 16; it++) {
        int lin = it * 256 + tid;
        int n = lin >> 6, m = lin & 63;
        __nv_bfloat16 hi, lo;
        bsplit(ts[m * 65 + n], hi, lo);
        g_Hth[(size_t)(n0 + n) * MPAD + m0 + m] = hi;
        g_Htl[(size_t)(n0 + n) * MPAD + m0 + m] = lo;
    }
}

// ============================ alpha (proxy destinations only) ============================
// blocks 0..99: proxies. blocks 100..127: zero pad rows of alphaP.
__global__ void k_alpha() {
    int tid = threadIdx.x;
    int p = blockIdx.x;
    if (p < NP) {
        __shared__ float sh[8];
        __shared__ float s_inv;
        float ldp = 0.f, lspp = 0.f;
        #pragma unroll
        for (int ti = 0; ti < 8; ti++) {
            ldp += g_lp[ti][p][1];
            lspp += g_lp[ti][p][0];
        }
        float w[4], sum = 0.f;
        #pragma unroll
        for (int i = 0; i < 4; i++) {
            int s = tid + i * 256;
            float ls = 0.f;
            #pragma unroll
            for (int ti = 0; ti < 8; ti++) ls += g_lp[ti][NP + s][0];
            w[i] = __expf(lrelu(ls + ldp));
            sum += w[i];
        }
        float wself = __expf(lrelu(lspp + ldp));
        #pragma unroll
        for (int o = 16; o > 0; o >>= 1) sum += __shfl_xor_sync(0xffffffffu, sum, o);
        if ((tid & 31) == 0) sh[tid >> 5] = sum;
        __syncthreads();
        if (tid == 0) {
            float ss = 0.f;
            #pragma unroll
            for (int i = 0; i < 8; i++) ss += sh[i];
            s_inv = 1.f / (ss + wself);
        }
        __syncthreads();
        float inv = s_inv;
        #pragma unroll
        for (int i = 0; i < 4; i++) {
            int col = NP + tid + i * 256;
            __nv_bfloat16 hi, lo;
            bsplit(w[i] * inv, hi, lo);
            g_aPh[(size_t)p * MPAD + col] = hi;
            g_aPl[(size_t)p * MPAD + col] = lo;
        }
        if (tid < NP) {
            float dv = (tid == p) ? wself * inv : 0.f;
            __nv_bfloat16 hi, lo;
            bsplit(dv, hi, lo);
            g_aPh[(size_t)p * MPAD + tid] = hi;
            g_aPl[(size_t)p * MPAD + tid] = lo;
        }
        if (tid < MPAD - NN) {
            __nv_bfloat16 z = __float2bfloat16(0.f);
            g_aPh[(size_t)p * MPAD + NN + tid] = z;
            g_aPl[(size_t)p * MPAD + NN + tid] = z;
        }
    } else {
        uint32_t* h = reinterpret_cast<uint32_t*>(g_aPh + (size_t)p * MPAD);
        uint32_t* l = reinterpret_cast<uint32_t*>(g_aPl + (size_t)p * MPAD);
        for (int i = tid; i < MPAD / 2; i += 256) { h[i] = 0u; l[i] = 0u; }
    }
}

// ============================ aggregation GEMM (tensor cores) ============================
// blocks 0..127: sample tiles — compute alpha in-block from g_lp into smem A, then GEMM.
// layer 1 only: blocks 128..271 proxy tiles x split-K (16 tiles x 9 splits).
// smem (sample blocks): [0,16K) Ah chunk0|1, [16K,32K) Al chunk0|1,
//                       [32K,64K) B stages (Bh|Bl x2), [64K, +768) lsp[128]+aself[64]
#define AGG_SMEM (65536 + 768)
__global__ void __launch_bounds__(256, 2) k_aggm(const float* __restrict__ bias,
                                                 float* __restrict__ hout, int layer) {
    extern __shared__ __align__(16) char sm[];
    int tid = threadIdx.x, wid = tid >> 5, lane = tid & 31;
    int wm = (wid >> 2) * 32, wn = (wid & 3) * 16;
    uint32_t sb = smem_u32(sm);
    int b = blockIdx.x;

    if (b < 128) {
        int m0 = (b >> 3) * 64, n0 = (b & 7) * 64;
        float* lsp = reinterpret_cast<float*>(sm + 65536);
        float* aself = lsp + 128;

        // issue both B chunks (K = node cols 0..127)
        int li = tid * 2;
        int lr0 = li >> 3, ls0 = li & 7;
        int lr1 = (li + 1) >> 3, ls1 = (li + 1) & 7;
        #pragma unroll
        for (int c = 0; c < 2; c++) {
            int kc = c * 64;
            uint32_t stb = sb + 32768 + c * 16384;
            cpa16(stb + SWB(lr0, ls0 * 16), g_Hth + (size_t)(n0 + lr0) * MPAD + kc + ls0 * 8);
            cpa16(stb + SWB(lr1, ls1 * 16), g_Hth + (size_t)(n0 + lr1) * MPAD + kc + ls1 * 8);
            cpa16(stb + 8192 + SWB(lr0, ls0 * 16), g_Htl + (size_t)(n0 + lr0) * MPAD + kc + ls0 * 8);
            cpa16(stb + 8192 + SWB(lr1, ls1 * 16), g_Htl + (size_t)(n0 + lr1) * MPAD + kc + ls1 * 8);
            asm volatile("cp.async.commit_group;");
        }

        // proxy l_src sums
        if (tid < NP) {
            float s = 0.f;
            #pragma unroll
            for (int ti = 0; ti < 8; ti++) s += g_lp[ti][tid][0];
            lsp[tid] = s;
        }
        __syncthreads();

        // alpha: each warp does 8 rows; lane covers cols lane*4..lane*4+3
        for (int rs = 0; rs < 8; rs++) {
            int rl = wid * 8 + rs;
            int node = NP + m0 + rl;
            float lsn = 0.f, ldn = 0.f;
            #pragma unroll
            for (int ti = 0; ti < 8; ti++) {
                lsn += g_lp[ti][node][0];
                ldn += g_lp[ti][node][1];
            }
            float w[4], sum = 0.f;
            #pragma unroll
            for (int j = 0; j < 4; j++) {
                int col = lane * 4 + j;
                w[j] = (col < NP) ? __expf(lrelu(lsp[col] + ldn)) : 0.f;
                sum += w[j];
            }
            float wself = __expf(lrelu(lsn + ldn));
            #pragma unroll
            for (int o = 16; o > 0; o >>= 1) sum += __shfl_xor_sync(0xffffffffu, sum, o);
            float inv = 1.f / (sum + wself);
            #pragma unroll
            for (int pp = 0; pp < 2; pp++) {
                int col = lane * 4 + pp * 2;
                int chunk = col >> 6, kc = col & 63;
                __nv_bfloat16 h0, l0, h1, l1;
                bsplit(w[pp * 2] * inv, h0, l0);
                bsplit(w[pp * 2 + 1] * inv, h1, l1);
                *reinterpret_cast<__nv_bfloat162*>(sm + chunk * 8192 + SWB(rl, kc * 2)) =
                    __nv_bfloat162(h0, h1);
                *reinterpret_cast<__nv_bfloat162*>(sm + 16384 + chunk * 8192 + SWB(rl, kc * 2)) =
                    __nv_bfloat162(l0, l1);
            }
            if (lane == 0) aself[rl] = wself * inv;
        }

        int a_r = (lane & 7) + ((lane >> 3) & 1) * 8;
        int a_kb = (lane >> 4) * 16;
        int b_r = lane & 7;
        int b_kb = ((lane >> 3) & 1) * 16;
        float acc[2][2][4] = {};

        asm volatile("cp.async.wait_group 0;");
        __syncthreads();

        #pragma unroll
        for (int c = 0; c < 2; c++) {
            uint32_t Ab = sb + c * 8192;
            uint32_t Bb = sb + 32768 + c * 16384;
            #pragma unroll
            for (int ks = 0; ks < 4; ks++) {
                int kb = ks * 32;
                uint32_t ah[2][4], al[2][4], bh[2][2], bl[2][2];
                #pragma unroll
                for (int mt = 0; mt < 2; mt++) {
                    int r = wm + mt * 16 + a_r;
                    ldm_x4(ah[mt], Ab + SWB(r, kb + a_kb));
                    ldm_x4(al[mt], Ab + 16384 + SWB(r, kb + a_kb));
                }
                #pragma unroll
                for (int nt = 0; nt < 2; nt++) {
                    int r = wn + nt * 8 + b_r;
                    ldm_x2(bh[nt], Bb + SWB(r, kb + b_kb));
                    ldm_x2(bl[nt], Bb + 8192 + SWB(r, kb + b_kb));
                }
                #pragma unroll
                for (int mt = 0; mt < 2; mt++)
                    #pragma unroll
                    for (int nt = 0; nt < 2; nt++) {
                        mma_bf16(acc[mt][nt], ah[mt], bh[nt]);
                        mma_bf16(acc[mt][nt], ah[mt], bl[nt]);
                        mma_bf16(acc[mt][nt], al[mt], bh[nt]);
                    }
            }
        }

        // epilogue: + aself*H_self + bias, relu -> bf16 split (+ fp32 h out on layer 2)
        #pragma unroll
        for (int mt = 0; mt < 2; mt++)
            #pragma unroll
            for (int nt = 0; nt < 2; nt++)
                #pragma unroll
                for (int j = 0; j < 4; j++) {
                    int rl = wm + mt * 16 + (lane >> 2) + (j >> 1) * 8;
                    int col = n0 + wn + nt * 8 + (lane & 3) * 2 + (j & 1);
                    float v = acc[mt][nt][j]
                            + aself[rl] * g_HW[(size_t)(NP + m0 + rl) * D + col] + bias[col];
                    acc[mt][nt][j] = v > 0.f ? v : 0.f;
                }
        #pragma unroll
        for (int mt = 0; mt < 2; mt++)
            #pragma unroll
            for (int half = 0; half < 2; half++) {
                int rl = wm + mt * 16 + (lane >> 2) + half * 8;
                int r = m0 + rl;
                int arow = (layer == 1) ? (NP + r) : r;
                #pragma unroll
                for (int nt = 0; nt < 2; nt++) {
                    int col = n0 + wn + nt * 8 + (lane & 3) * 2;
                    float v0 = acc[mt][nt][half * 2], v1 = acc[mt][nt][half * 2 + 1];
                    __nv_bfloat16 h0, h1, l0, l1;
                    bsplit(v0, h0, l0); bsplit(v1, h1, l1);
                    *reinterpret_cast<__nv_bfloat162*>(g_Ah + (size_t)arow * D + col) =
                        __nv_bfloat162(h0, h1);
                    *reinterpret_cast<__nv_bfloat162*>(g_Al + (size_t)arow * D + col) =
                        __nv_bfloat162(l0, l1);
                    if (layer == 2)
                        *reinterpret_cast<float2*>(hout + (size_t)r * D + col) =
                            make_float2(v0, v1);
                }
            }
    } else {
        int bb = b - 128;
        int tile = bb & 15;
        int z = bb >> 4;                       // split index 0..8
        int m0 = (tile >> 3) * 64, n0 = (tile & 7) * 64;
        MMA_MAINLOOP(g_aPh, g_aPl, g_Hth, g_Htl, MPAD, MPAD, 2, z * 128)
        float* part = &g_ppart[z][0][0];
        #pragma unroll
        for (int mt = 0; mt < 2; mt++)
            #pragma unroll
            for (int half = 0; half < 2; half++) {
                int p = m0 + wm + mt * 16 + (lane >> 2) + half * 8;
                if (p >= NP) continue;
                #pragma unroll
                for (int nt = 0; nt < 2; nt++) {
                    int col = n0 + wn + nt * 8 + (lane & 3) * 2;
                    *reinterpret_cast<float2*>(part + (size_t)p * D + col) =
                        make_float2(acc[mt][nt][half * 2], acc[mt][nt][half * 2 + 1]);
                }
            }
    }
}

// proxy finalize: sum 9 split-K partials + bias, relu -> bf16 split rows 0..99 of g_Ah/g_Al
__global__ void k_pfin(const float* __restrict__ bias) {
    int idx = blockIdx.x * 256 + threadIdx.x;
    int p = idx / (D / 2);
    int c = (idx - p * (D / 2)) * 2;
    float v0 = 0.f, v1 = 0.f;
    #pragma unroll
    for (int z = 0; z < PSPLIT; z++) {
        float2 t = *reinterpret_cast<const float2*>(&g_ppart[z][p][c]);
        v0 += t.x; v1 += t.y;
    }
    v0 += bias[c];     v0 = v0 > 0.f ? v0 : 0.f;
    v1 += bias[c + 1]; v1 = v1 > 0.f ? v1 : 0.f;
    __nv_bfloat16 h0, h1, l0, l1;
    bsplit(v0, h0, l0); bsplit(v1, h1, l1);
    *reinterpret_cast<__nv_bfloat162*>(g_Ah + (size_t)p * D + c) = __nv_bfloat162(h0, h1);
    *reinterpret_cast<__nv_bfloat162*>(g_Al + (size_t)p * D + c) = __nv_bfloat162(l0, l1);
}

// ============================ launch ============================
extern "C" void kernel_launch(void* const* d_in, const int* in_sizes, int n_in,
                              void* d_out, int out_size) {
    const float* x    = (const float*)d_in[0];
    const float* prox = (const float*)d_in[1];
    const float* W1   = (const float*)d_in[2];
    const float* as1  = (const float*)d_in[3];
    const float* ad1  = (const float*)d_in[4];
    const float* b1   = (const float*)d_in[5];
    const float* W2   = (const float*)d_in[6];
    const float* as2  = (const float*)d_in[7];
    const float* ad2  = (const float*)d_in[8];
    const float* b2   = (const float*)d_in[9];
    const float* fcw  = (const float*)d_in[10];
    const float* fcb  = (const float*)d_in[11];
    float* out = (float*)d_out;

    __nv_bfloat16 *pAh, *pAl, *pW1h, *pW1l, *pW2h, *pW2l, *pFCh, *pFCl;
    cudaGetSymbolAddress((void**)&pAh,  g_Ah);
    cudaGetSymbolAddress((void**)&pAl,  g_Al);
    cudaGetSymbolAddress((void**)&pW1h, g_W1h);
    cudaGetSymbolAddress((void**)&pW1l, g_W1l);
    cudaGetSymbolAddress((void**)&pW2h, g_W2h);
    cudaGetSymbolAddress((void**)&pW2l, g_W2l);
    cudaGetSymbolAddress((void**)&pFCh, g_FCh);
    cudaGetSymbolAddress((void**)&pFCl, g_FCl);

    cudaFuncSetAttribute(k_mma,  cudaFuncAttributeMaxDynamicSharedMemorySize, 2 * STAGE_BYTES);
    cudaFuncSetAttribute(k_aggm, cudaFuncAttributeMaxDynamicSharedMemorySize, AGG_SMEM);

    k_setup<<<1152, 256>>>(W1, W2, fcw, x, prox);

    // ---- layer 1
    k_mma<<<dim3(8, 18), 256, 2 * STAGE_BYTES>>>(pAh, pAl, pW1h, pW1l, nullptr, nullptr, 1, as1, ad1);
    k_alpha<<<128, 256>>>();
    k_aggm<<<128 + 16 * PSPLIT, 256, AGG_SMEM>>>(b1, nullptr, 1);
    k_pfin<<<NP * D / 512, 256>>>(b1);

    // ---- layer 2 (proxy aggregation unused downstream)
    k_mma<<<dim3(8, 18), 256, 2 * STAGE_BYTES>>>(pAh, pAl, pW2h, pW2l, nullptr, nullptr, 1, as2, ad2);
    k_aggm<<<128, 256, AGG_SMEM>>>(b2, out + NS * 100, 2);

    // ---- preds = h @ fc_w + fc_b
    k_mma<<<dim3(2, 16), 256, 2 * STAGE_BYTES>>>(pAh, pAl, pFCh, pFCl, out, fcb, 0, nullptr, nullptr);
}

// round 13
// speedup vs baseline: 1.1114x; 1.1114x over previous
#include <cuda_runtime.h>
#include <cuda_bf16.h>
#include <cstdint>

#define NP 100      // proxies
#define NS 1024     // samples
#define NN 1124     // total nodes
#define MPAD 1152   // NN padded to 128
#define D  512
#define KPAD2 128   // NP padded for sample-agg K
#define PSPLIT 9    // proxy-agg split-K factor (9 x 128 = 1152)

// scratch (device globals; no allocation allowed)
__device__ float g_HW[MPAD * D];
__device__ float g_aselfS[NS];
__device__ float g_lp[8][NN][2];        // logit partials [64col-tile][node][src/dst]
__device__ float g_ppart[PSPLIT][128][D];
// bf16 split operands
__device__ __nv_bfloat16 g_Ah[MPAD * D];
__device__ __nv_bfloat16 g_Al[MPAD * D];
__device__ __nv_bfloat16 g_W1h[D * D];
__device__ __nv_bfloat16 g_W1l[D * D];
__device__ __nv_bfloat16 g_W2h[D * D];
__device__ __nv_bfloat16 g_W2l[D * D];
__device__ __nv_bfloat16 g_FCh[128 * D];
__device__ __nv_bfloat16 g_FCl[128 * D];
__device__ __nv_bfloat16 g_Hth[D * MPAD];   // H transposed [d][node]
__device__ __nv_bfloat16 g_Htl[D * MPAD];
__device__ __nv_bfloat16 g_aSh[NS * KPAD2]; // alpha (sample dst), K-major
__device__ __nv_bfloat16 g_aSl[NS * KPAD2];
__device__ __nv_bfloat16 g_aPh[128 * MPAD]; // alpha (proxy dst), K over all nodes, self on diag
__device__ __nv_bfloat16 g_aPl[128 * MPAD];

__device__ __forceinline__ float lrelu(float v) { return v > 0.f ? v : 0.2f * v; }

__device__ __forceinline__ uint32_t smem_u32(const void* p) {
    uint32_t a;
    asm("{ .reg .u64 t; cvta.to.shared.u64 t, %1; cvt.u32.u64 %0, t; }" : "=r"(a) : "l"(p));
    return a;
}
__device__ __forceinline__ void bsplit(float v, __nv_bfloat16& hi, __nv_bfloat16& lo) {
    hi = __float2bfloat16(v);
    lo = __float2bfloat16(v - __bfloat162float(hi));
}

// ============================ setup: W splits + input convert ============================
__global__ void k_setup(const float* __restrict__ W1, const float* __restrict__ W2,
                        const float* __restrict__ fcw,
                        const float* __restrict__ x, const float* __restrict__ prox) {
    int b = blockIdx.x;
    if (b < 512) {
        const float* W = (b >= 256) ? W2 : W1;
        __nv_bfloat16* Wh = (b >= 256) ? g_W2h : g_W1h;
        __nv_bfloat16* Wl = (b >= 256) ? g_W2l : g_W1l;
        int bb = b & 255;
        __shared__ float t[32][33];
        int tx = threadIdx.x & 31, ty = threadIdx.x >> 5;
        int n0 = (bb & 15) * 32, k0 = (bb >> 4) * 32;
        #pragma unroll
        for (int j = 0; j < 4; j++)
            t[ty + 8 * j][tx] = W[(size_t)(k0 + ty + 8 * j) * D + n0 + tx];
        __syncthreads();
        #pragma unroll
        for (int j = 0; j < 4; j++) {
            int n = n0 + ty + 8 * j, k = k0 + tx;
            __nv_bfloat16 hi, lo;
            bsplit(t[tx][ty + 8 * j], hi, lo);
            Wh[(size_t)n * D + k] = hi;
            Wl[(size_t)n * D + k] = lo;
        }
    } else if (b < 576) {
        int bb = b - 512;
        __shared__ float t[32][33];
        int tx = threadIdx.x & 31, ty = threadIdx.x >> 5;
        int n0 = (bb & 3) * 32, k0 = (bb >> 2) * 32;
        #pragma unroll
        for (int j = 0; j < 4; j++) {
            int n = n0 + tx;
            t[ty + 8 * j][tx] = (n < 100) ? fcw[(size_t)(k0 + ty + 8 * j) * 100 + n] : 0.f;
        }
        __syncthreads();
        #pragma unroll
        for (int j = 0; j < 4; j++) {
            int n = n0 + ty + 8 * j, k = k0 + tx;
            __nv_bfloat16 hi, lo;
            bsplit(t[tx][ty + 8 * j], hi, lo);
            g_FCh[(size_t)n * D + k] = hi;
            g_FCl[(size_t)n * D + k] = lo;
        }
    } else {
        int row = (b - 576) * 2 + (threadIdx.x >> 7);
        int c4 = (threadIdx.x & 127) * 4;
        int base = row * D + c4;
        float4 v = make_float4(0.f, 0.f, 0.f, 0.f);
        if (row < NP)      v = *reinterpret_cast<const float4*>(prox + base);
        else if (row < NN) v = *reinterpret_cast<const float4*>(x + base - NP * D);
        __nv_bfloat16 h0, h1, h2, h3, l0, l1, l2, l3;
        bsplit(v.x, h0, l0); bsplit(v.y, h1, l1); bsplit(v.z, h2, l2); bsplit(v.w, h3, l3);
        *reinterpret_cast<__nv_bfloat162*>(g_Ah + base)     = __nv_bfloat162(h0, h1);
        *reinterpret_cast<__nv_bfloat162*>(g_Ah + base + 2) = __nv_bfloat162(h2, h3);
        *reinterpret_cast<__nv_bfloat162*>(g_Al + base)     = __nv_bfloat162(l0, l1);
        *reinterpret_cast<__nv_bfloat162*>(g_Al + base + 2) = __nv_bfloat162(l2, l3);
    }
}

// ============================ mma common ============================
#define SWB(r, b) ((r) * 128 + ((b) ^ (((r) & 7) << 4)))
#define STAGE_BYTES 32768
#define AGG_SMEM (2 * STAGE_BYTES + 16384)   // + fp32 self tile

__device__ __forceinline__ void ldm_x4(uint32_t* f, uint32_t addr) {
    asm volatile("ldmatrix.sync.aligned.m8n8.x4.shared.b16 {%0,%1,%2,%3}, [%4];"
                 : "=r"(f[0]), "=r"(f[1]), "=r"(f[2]), "=r"(f[3]) : "r"(addr));
}
__device__ __forceinline__ void ldm_x2(uint32_t* f, uint32_t addr) {
    asm volatile("ldmatrix.sync.aligned.m8n8.x2.shared.b16 {%0,%1}, [%2];"
                 : "=r"(f[0]), "=r"(f[1]) : "r"(addr));
}
__device__ __forceinline__ void mma_bf16(float* c, const uint32_t* a, const uint32_t* b) {
    asm volatile(
        "mma.sync.aligned.m16n8k16.row.col.f32.bf16.bf16.f32 "
        "{%0,%1,%2,%3}, {%4,%5,%6,%7}, {%8,%9}, {%0,%1,%2,%3};"
        : "+f"(c[0]), "+f"(c[1]), "+f"(c[2]), "+f"(c[3])
        : "r"(a[0]), "r"(a[1]), "r"(a[2]), "r"(a[3]), "r"(b[0]), "r"(b[1]));
}
__device__ __forceinline__ void cpa16(uint32_t saddr, const void* g) {
    asm volatile("cp.async.cg.shared.global [%0], [%1], 16;" :: "r"(saddr), "l"(g));
}

#define MMA_MAINLOOP(AH, AL, BH, BL, LDA, LDB, NCHUNK, KOFF)                             \
    int li = tid * 2;                                                                    \
    int lr0 = li >> 3, ls0 = li & 7;                                                     \
    int lr1 = (li + 1) >> 3, ls1 = (li + 1) & 7;                                         \
    int a_r = (lane & 7) + ((lane >> 3) & 1) * 8;                                        \
    int a_kb = (lane >> 4) * 16;                                                         \
    int b_r = lane & 7;                                                                  \
    int b_kb = ((lane >> 3) & 1) * 16;                                                   \
    float acc[2][2][4] = {};                                                             \
    auto issue = [&](int c, int st) {                                                    \
        int kc = (KOFF) + c * 64;                                                        \
        uint32_t stb = sb + st * STAGE_BYTES;                                            \
        cpa16(stb + SWB(lr0, ls0 * 16), (AH) + (size_t)(m0 + lr0) * (LDA) + kc + ls0 * 8); \
        cpa16(stb + SWB(lr1, ls1 * 16), (AH) + (size_t)(m0 + lr1) * (LDA) + kc + ls1 * 8); \
        cpa16(stb + 8192 + SWB(lr0, ls0 * 16), (AL) + (size_t)(m0 + lr0) * (LDA) + kc + ls0 * 8); \
        cpa16(stb + 8192 + SWB(lr1, ls1 * 16), (AL) + (size_t)(m0 + lr1) * (LDA) + kc + ls1 * 8); \
        cpa16(stb + 16384 + SWB(lr0, ls0 * 16), (BH) + (size_t)(n0 + lr0) * (LDB) + kc + ls0 * 8); \
        cpa16(stb + 16384 + SWB(lr1, ls1 * 16), (BH) + (size_t)(n0 + lr1) * (LDB) + kc + ls1 * 8); \
        cpa16(stb + 24576 + SWB(lr0, ls0 * 16), (BL) + (size_t)(n0 + lr0) * (LDB) + kc + ls0 * 8); \
        cpa16(stb + 24576 + SWB(lr1, ls1 * 16), (BL) + (size_t)(n0 + lr1) * (LDB) + kc + ls1 * 8); \
        asm volatile("cp.async.commit_group;");                                          \
    };                                                                                   \
    issue(0, 0);                                                                         \
    asm volatile("cp.async.wait_group 0;");                                              \
    __syncthreads();                                                                     \
    for (int c = 0; c < (NCHUNK); c++) {                                                 \
        int st = c & 1;                                                                  \
        if (c + 1 < (NCHUNK)) issue(c + 1, st ^ 1);                                      \
        uint32_t stb = sb + st * STAGE_BYTES;                                            \
        _Pragma("unroll")                                                                \
        for (int ks = 0; ks < 4; ks++) {                                                 \
            int kb = ks * 32;                                                            \
            uint32_t ah[2][4], al[2][4], bh[2][2], bl[2][2];                             \
            _Pragma("unroll")                                                            \
            for (int mt = 0; mt < 2; mt++) {                                             \
                int r = wm + mt * 16 + a_r;                                              \
                ldm_x4(ah[mt], stb + 0    + SWB(r, kb + a_kb));                          \
                ldm_x4(al[mt], stb + 8192 + SWB(r, kb + a_kb));                          \
            }                                                                            \
            _Pragma("unroll")                                                            \
            for (int nt = 0; nt < 2; nt++) {                                             \
                int r = wn + nt * 8 + b_r;                                               \
                ldm_x2(bh[nt], stb + 16384 + SWB(r, kb + b_kb));                         \
                ldm_x2(bl[nt], stb + 24576 + SWB(r, kb + b_kb));                         \
            }                                                                            \
            _Pragma("unroll")                                                            \
            for (int mt = 0; mt < 2; mt++)                                               \
                _Pragma("unroll")                                                        \
                for (int nt = 0; nt < 2; nt++) {                                         \
                    mma_bf16(acc[mt][nt], ah[mt], bh[nt]);                               \
                    mma_bf16(acc[mt][nt], ah[mt], bl[nt]);                               \
                    mma_bf16(acc[mt][nt], al[mt], bh[nt]);                               \
                }                                                                        \
        }                                                                                \
        if (c + 1 < (NCHUNK)) asm volatile("cp.async.wait_group 0;");                    \
        __syncthreads();                                                                 \
    }

// ============================ layer GEMM / FC GEMM ============================
__global__ void __launch_bounds__(256, 2) k_mma(
    const __nv_bfloat16* __restrict__ Ah, const __nv_bfloat16* __restrict__ Al,
    const __nv_bfloat16* __restrict__ Bh, const __nv_bfloat16* __restrict__ Bl,
    float* __restrict__ C, const float* __restrict__ bias, int mode,
    const float* __restrict__ asrc, const float* __restrict__ adst) {
    extern __shared__ __align__(16) char sm[];
    int tid = threadIdx.x, wid = tid >> 5, lane = tid & 31;
    int n0 = blockIdx.x * 64, m0 = blockIdx.y * 64;
    int wm = (wid >> 2) * 32, wn = (wid & 3) * 16;
    uint32_t sb = smem_u32(sm);

    MMA_MAINLOOP(Ah, Al, Bh, Bl, D, D, 8, 0)

    if (mode == 0) {
        #pragma unroll
        for (int mt = 0; mt < 2; mt++) {
            int row = m0 + wm + mt * 16 + (lane >> 2);
            #pragma unroll
            for (int nt = 0; nt < 2; nt++) {
                int col = n0 + wn + nt * 8 + (lane & 3) * 2;
                if (col >= 100) continue;
                float b0 = bias[col], b1 = bias[col + 1];
                *reinterpret_cast<float2*>(C + (size_t)row * 100 + col) =
                    make_float2(acc[mt][nt][0] + b0, acc[mt][nt][1] + b1);
                *reinterpret_cast<float2*>(C + (size_t)(row + 8) * 100 + col) =
                    make_float2(acc[mt][nt][2] + b0, acc[mt][nt][3] + b1);
            }
        }
        return;
    }

    // fp32 HW store
    #pragma unroll
    for (int mt = 0; mt < 2; mt++) {
        int row = m0 + wm + mt * 16 + (lane >> 2);
        #pragma unroll
        for (int nt = 0; nt < 2; nt++) {
            int col = n0 + wn + nt * 8 + (lane & 3) * 2;
            *reinterpret_cast<float2*>(g_HW + (size_t)row * D + col) =
                make_float2(acc[mt][nt][0], acc[mt][nt][1]);
            *reinterpret_cast<float2*>(g_HW + (size_t)(row + 8) * D + col) =
                make_float2(acc[mt][nt][2], acc[mt][nt][3]);
        }
    }

    // logit partials
    {
        float* lpb = reinterpret_cast<float*>(sm);   // [64][4][2]
        #pragma unroll
        for (int mt = 0; mt < 2; mt++)
            #pragma unroll
            for (int half = 0; half < 2; half++) {
                int rl = wm + mt * 16 + (lane >> 2) + half * 8;
                float s = 0.f, t = 0.f;
                #pragma unroll
                for (int nt = 0; nt < 2; nt++) {
                    int col = n0 + wn + nt * 8 + (lane & 3) * 2;
                    float v0 = acc[mt][nt][half * 2], v1 = acc[mt][nt][half * 2 + 1];
                    s += v0 * asrc[col] + v1 * asrc[col + 1];
                    t += v0 * adst[col] + v1 * adst[col + 1];
                }
                s += __shfl_xor_sync(0xffffffffu, s, 1);
                s += __shfl_xor_sync(0xffffffffu, s, 2);
                t += __shfl_xor_sync(0xffffffffu, t, 1);
                t += __shfl_xor_sync(0xffffffffu, t, 2);
                if ((lane & 3) == 0) {
                    lpb[(rl * 4 + (wid & 3)) * 2 + 0] = s;
                    lpb[(rl * 4 + (wid & 3)) * 2 + 1] = t;
                }
            }
        __syncthreads();
        if (tid < 128) {
            int rl = tid >> 1, comp = tid & 1;
            int row = m0 + rl;
            if (row < NN) {
                float s = lpb[(rl * 4 + 0) * 2 + comp] + lpb[(rl * 4 + 1) * 2 + comp]
                        + lpb[(rl * 4 + 2) * 2 + comp] + lpb[(rl * 4 + 3) * 2 + comp];
                g_lp[n0 >> 6][row][comp] = s;
            }
        }
        __syncthreads();
    }

    // transpose via smem, write Ht bf16 split
    float* ts = reinterpret_cast<float*>(sm);   // [64][65]
    #pragma unroll
    for (int mt = 0; mt < 2; mt++)
        #pragma unroll
        for (int nt = 0; nt < 2; nt++)
            #pragma unroll
            for (int j = 0; j < 4; j++) {
                int rl = wm + mt * 16 + (lane >> 2) + (j >> 1) * 8;
                int cl = wn + nt * 8 + (lane & 3) * 2 + (j & 1);
                ts[rl * 65 + cl] = acc[mt][nt][j];
            }
    __syncthreads();
    #pragma unroll
    for (int it = 0; it < 16; it++) {
        int lin = it * 256 + tid;
        int n = lin >> 6, m = lin & 63;
        __nv_bfloat16 hi, lo;
        bsplit(ts[m * 65 + n], hi, lo);
        g_Hth[(size_t)(n0 + n) * MPAD + m0 + m] = hi;
        g_Htl[(size_t)(n0 + n) * MPAD + m0 + m] = lo;
    }
}

// ============================ alpha (from g_lp; no max subtraction) ============================
__global__ void k_alpha(int layer) {
    int tid = threadIdx.x;
    int b = blockIdx.x;
    if (b < 128) {
        __shared__ float lsp[128];
        if (tid < NP) {
            float s = 0.f;
            #pragma unroll
            for (int ti = 0; ti < 8; ti++)
                s += reinterpret_cast<const float2*>(&g_lp[ti][tid][0])->x;
            lsp[tid] = s;
        }
        __syncthreads();
        int warp = b * 8 + (tid >> 5);
        int lane = tid & 31;
        int node = NP + warp;
        float lsn = 0.f, ldn = 0.f;
        #pragma unroll
        for (int ti = 0; ti < 8; ti++) {
            float2 v = *reinterpret_cast<const float2*>(&g_lp[ti][node][0]);
            lsn += v.x;
            ldn += v.y;
        }
        float w[4], sum = 0.f;
        #pragma unroll
        for (int i = 0; i < 4; i++) {
            int p = lane + 32 * i;
            w[i] = (p < NP) ? __expf(lrelu(lsp[p] + ldn)) : 0.f;
            sum += w[i];
        }
        float wself = __expf(lrelu(lsn + ldn));
        #pragma unroll
        for (int o = 16; o > 0; o >>= 1) sum += __shfl_xor_sync(0xffffffffu, sum, o);
        float inv = 1.f / (sum + wself);
        #pragma unroll
        for (int i = 0; i < 4; i++) {
            int p = lane + 32 * i;
            __nv_bfloat16 hi, lo;
            bsplit(w[i] * inv, hi, lo);
            g_aSh[(size_t)warp * KPAD2 + p] = hi;
            g_aSl[(size_t)warp * KPAD2 + p] = lo;
        }
        if (lane == 0) g_aselfS[warp] = wself * inv;
    } else if (b < 228) {
        __shared__ float sh[8];
        __shared__ float s_inv;
        int p = b - 128;
        float ldp = 0.f, lspp = 0.f;
        #pragma unroll
        for (int ti = 0; ti < 8; ti++) {
            float2 v = *reinterpret_cast<const float2*>(&g_lp[ti][p][0]);
            lspp += v.x;
            ldp += v.y;
        }
        float w[4], sum = 0.f;
        #pragma unroll
        for (int i = 0; i < 4; i++) {
            int s = tid + i * 256;
            float ls = 0.f;
            #pragma unroll
            for (int ti = 0; ti < 8; ti++)
                ls += reinterpret_cast<const float2*>(&g_lp[ti][NP + s][0])->x;
            w[i] = __expf(lrelu(ls + ldp));
            sum += w[i];
        }
        float wself = __expf(lrelu(lspp + ldp));
        #pragma unroll
        for (int o = 16; o > 0; o >>= 1) sum += __shfl_xor_sync(0xffffffffu, sum, o);
        if ((tid & 31) == 0) sh[tid >> 5] = sum;
        __syncthreads();
        if (tid == 0) {
            float ss = 0.f;
            #pragma unroll
            for (int i = 0; i < 8; i++) ss += sh[i];
            s_inv = 1.f / (ss + wself);
        }
        __syncthreads();
        float inv = s_inv;
        #pragma unroll
        for (int i = 0; i < 4; i++) {
            int col = NP + tid + i * 256;
            __nv_bfloat16 hi, lo;
            bsplit(w[i] * inv, hi, lo);
            g_aPh[(size_t)p * MPAD + col] = hi;
            g_aPl[(size_t)p * MPAD + col] = lo;
        }
        if (tid < NP) {
            float dv = (tid == p) ? wself * inv : 0.f;
            __nv_bfloat16 hi, lo;
            bsplit(dv, hi, lo);
            g_aPh[(size_t)p * MPAD + tid] = hi;
            g_aPl[(size_t)p * MPAD + tid] = lo;
        }
        if (tid < MPAD - NN) {
            __nv_bfloat16 z = __float2bfloat16(0.f);
            g_aPh[(size_t)p * MPAD + NN + tid] = z;
            g_aPl[(size_t)p * MPAD + NN + tid] = z;
        }
    } else {
        int p = 100 + (b - 228);
        uint32_t* h = reinterpret_cast<uint32_t*>(g_aPh + (size_t)p * MPAD);
        uint32_t* l = reinterpret_cast<uint32_t*>(g_aPl + (size_t)p * MPAD);
        for (int i = tid; i < MPAD / 2; i += 256) { h[i] = 0u; l[i] = 0u; }
    }
}

// ============================ aggregation GEMM (tensor cores) ============================
// blocks 0..127 sample tiles (K=128) with self-tile prefetch into smem.
// layer 1 only: blocks 128..271 proxy tiles x split-K (16 tiles x 9 splits).
__global__ void __launch_bounds__(256, 2) k_aggm(const float* __restrict__ bias,
                                                 float* __restrict__ hout, int layer) {
    extern __shared__ __align__(16) char sm[];
    int tid = threadIdx.x, wid = tid >> 5, lane = tid & 31;
    int wm = (wid >> 2) * 32, wn = (wid & 3) * 16;
    uint32_t sb = smem_u32(sm);
    int b = blockIdx.x;

    if (b < 128) {
        int m0 = (b >> 3) * 64, n0 = (b & 7) * 64;

        // prefetch fp32 self tile HW[NP+m0 .. +64, n0 .. +64] into sm+64K (own group;
        // covered by the mainloop's wait_group 0)
        #pragma unroll
        for (int q = 0; q < 4; q++) {
            int i = tid + q * 256;              // 0..1023 float4 slots
            int r = i >> 4, cc = (i & 15) * 4;
            cpa16(sb + 65536 + i * 16, g_HW + (size_t)(NP + m0 + r) * D + n0 + cc);
        }
        asm volatile("cp.async.commit_group;");

        MMA_MAINLOOP(g_aSh, g_aSl, g_Hth, g_Htl, KPAD2, MPAD, 2, 0)

        const float* selfS = reinterpret_cast<const float*>(sm + 65536);
        #pragma unroll
        for (int mt = 0; mt < 2; mt++)
            #pragma unroll
            for (int nt = 0; nt < 2; nt++)
                #pragma unroll
                for (int j = 0; j < 4; j++) {
                    int rl = wm + mt * 16 + (lane >> 2) + (j >> 1) * 8;
                    int cl = wn + nt * 8 + (lane & 3) * 2 + (j & 1);
                    float v = acc[mt][nt][j] + g_aselfS[m0 + rl] * selfS[rl * 64 + cl]
                            + bias[n0 + cl];
                    acc[mt][nt][j] = v > 0.f ? v : 0.f;
                }
        #pragma unroll
        for (int mt = 0; mt < 2; mt++)
            #pragma unroll
            for (int half = 0; half < 2; half++) {
                int r = m0 + wm + mt * 16 + (lane >> 2) + half * 8;
                int arow = (layer == 1) ? (NP + r) : r;
                #pragma unroll
                for (int nt = 0; nt < 2; nt++) {
                    int col = n0 + wn + nt * 8 + (lane & 3) * 2;
                    float v0 = acc[mt][nt][half * 2], v1 = acc[mt][nt][half * 2 + 1];
                    __nv_bfloat16 h0, h1, l0, l1;
                    bsplit(v0, h0, l0); bsplit(v1, h1, l1);
                    *reinterpret_cast<__nv_bfloat162*>(g_Ah + (size_t)arow * D + col) =
                        __nv_bfloat162(h0, h1);
                    *reinterpret_cast<__nv_bfloat162*>(g_Al + (size_t)arow * D + col) =
                        __nv_bfloat162(l0, l1);
                    if (layer == 2)
                        *reinterpret_cast<float2*>(hout + (size_t)r * D + col) =
                            make_float2(v0, v1);
                }
            }
    } else {
        int bb = b - 128;
        int tile = bb & 15;
        int z = bb >> 4;                       // split index 0..8
        int m0 = (tile >> 3) * 64, n0 = (tile & 7) * 64;
        MMA_MAINLOOP(g_aPh, g_aPl, g_Hth, g_Htl, MPAD, MPAD, 2, z * 128)
        float* part = &g_ppart[z][0][0];
        #pragma unroll
        for (int mt = 0; mt < 2; mt++)
            #pragma unroll
            for (int half = 0; half < 2; half++) {
                int p = m0 + wm + mt * 16 + (lane >> 2) + half * 8;
                if (p >= NP) continue;
                #pragma unroll
                for (int nt = 0; nt < 2; nt++) {
                    int col = n0 + wn + nt * 8 + (lane & 3) * 2;
                    *reinterpret_cast<float2*>(part + (size_t)p * D + col) =
                        make_float2(acc[mt][nt][half * 2], acc[mt][nt][half * 2 + 1]);
                }
            }
    }
}

// proxy finalize: sum 9 split-K partials + bias, relu -> bf16 split rows 0..99 of g_Ah/g_Al
__global__ void k_pfin(const float* __restrict__ bias) {
    int idx = blockIdx.x * 256 + threadIdx.x;
    int p = idx / (D / 2);
    int c = (idx - p * (D / 2)) * 2;
    float v0 = 0.f, v1 = 0.f;
    #pragma unroll
    for (int z = 0; z < PSPLIT; z++) {
        float2 t = *reinterpret_cast<const float2*>(&g_ppart[z][p][c]);
        v0 += t.x; v1 += t.y;
    }
    v0 += bias[c];     v0 = v0 > 0.f ? v0 : 0.f;
    v1 += bias[c + 1]; v1 = v1 > 0.f ? v1 : 0.f;
    __nv_bfloat16 h0, h1, l0, l1;
    bsplit(v0, h0, l0); bsplit(v1, h1, l1);
    *reinterpret_cast<__nv_bfloat162*>(g_Ah + (size_t)p * D + c) = __nv_bfloat162(h0, h1);
    *reinterpret_cast<__nv_bfloat162*>(g_Al + (size_t)p * D + c) = __nv_bfloat162(l0, l1);
}

// ============================ launch ============================
extern "C" void kernel_launch(void* const* d_in, const int* in_sizes, int n_in,
                              void* d_out, int out_size) {
    const float* x    = (const float*)d_in[0];
    const float* prox = (const float*)d_in[1];
    const float* W1   = (const float*)d_in[2];
    const float* as1  = (const float*)d_in[3];
    const float* ad1  = (const float*)d_in[4];
    const float* b1   = (const float*)d_in[5];
    const float* W2   = (const float*)d_in[6];
    const float* as2  = (const float*)d_in[7];
    const float* ad2  = (const float*)d_in[8];
    const float* b2   = (const float*)d_in[9];
    const float* fcw  = (const float*)d_in[10];
    const float* fcb  = (const float*)d_in[11];
    float* out = (float*)d_out;

    __nv_bfloat16 *pAh, *pAl, *pW1h, *pW1l, *pW2h, *pW2l, *pFCh, *pFCl;
    cudaGetSymbolAddress((void**)&pAh,  g_Ah);
    cudaGetSymbolAddress((void**)&pAl,  g_Al);
    cudaGetSymbolAddress((void**)&pW1h, g_W1h);
    cudaGetSymbolAddress((void**)&pW1l, g_W1l);
    cudaGetSymbolAddress((void**)&pW2h, g_W2h);
    cudaGetSymbolAddress((void**)&pW2l, g_W2l);
    cudaGetSymbolAddress((void**)&pFCh, g_FCh);
    cudaGetSymbolAddress((void**)&pFCl, g_FCl);

    cudaFuncSetAttribute(k_mma,  cudaFuncAttributeMaxDynamicSharedMemorySize, 2 * STAGE_BYTES);
    cudaFuncSetAttribute(k_aggm, cudaFuncAttributeMaxDynamicSharedMemorySize, AGG_SMEM);

    k_setup<<<1152, 256>>>(W1, W2, fcw, x, prox);

    // ---- layer 1
    k_mma<<<dim3(8, 18), 256, 2 * STAGE_BYTES>>>(pAh, pAl, pW1h, pW1l, nullptr, nullptr, 1, as1, ad1);
    k_alpha<<<256, 256>>>(1);
    k_aggm<<<128 + 16 * PSPLIT, 256, AGG_SMEM>>>(b1, nullptr, 1);
    k_pfin<<<NP * D / 512, 256>>>(b1);

    // ---- layer 2 (proxy aggregation unused downstream)
    k_mma<<<dim3(8, 18), 256, 2 * STAGE_BYTES>>>(pAh, pAl, pW2h, pW2l, nullptr, nullptr, 1, as2, ad2);
    k_alpha<<<128, 256>>>(2);
    k_aggm<<<128, 256, AGG_SMEM>>>(b2, out + NS * 100, 2);

    // ---- preds = h @ fc_w + fc_b
    k_mma<<<dim3(2, 16), 256, 2 * STAGE_BYTES>>>(pAh, pAl, pFCh, pFCl, out, fcb, 0, nullptr, nullptr);
}